// round 11
// baseline (speedup 1.0000x reference)
#include <cuda_runtime.h>
#include <cstdint>

// Problem constants
#define BC    2
#define NQC   2048
#define NKC   2048
#define DIMC  1024
#define HC    16
#define HDC   32
#define D2C   64
#define LAMBDA_INIT_F 0.6192834728526787f
#define ONE_MINUS_LAMBDA_F 0.3807165271473213f
#define SCALE_F 0.17677669529663687f
// SCALE * log2(e): scores computed in log2 domain, exponentiated via ex2
#define SCALE_L2E_F (0.17677669529663687f * 1.44269504088896340f)
#define EPS_F 1e-5f

// Scratch (device globals — no runtime allocation allowed)
__device__ float g_Q[(size_t)BC * NQC * DIMC];
__device__ float g_K[(size_t)BC * NKC * DIMC];
__device__ float g_V[(size_t)BC * NKC * DIMC];
__device__ float g_A[(size_t)BC * NQC * DIMC];
// tf32-rounded operand copies (prepass output)
__device__ float g_rq[(size_t)BC * NQC * DIMC];
__device__ float g_rk[(size_t)BC * NKC * DIMC];
__device__ float g_rv[(size_t)BC * NKC * DIMC];
__device__ float g_rWq[(size_t)DIMC * DIMC];
__device__ float g_rWk[(size_t)DIMC * DIMC];
__device__ float g_rWv[(size_t)DIMC * DIMC];
__device__ float g_rWp[(size_t)DIMC * DIMC];
__device__ float g_lam;

// ---------------------------------------------------------------------------
// helpers
// ---------------------------------------------------------------------------
__device__ __forceinline__ uint32_t f2tf(float x) {
    uint32_t u;
    asm("cvt.rna.tf32.f32 %0, %1;" : "=r"(u) : "f"(x));
    return u;
}
__device__ __forceinline__ float f2tff(float x) {
    return __uint_as_float(f2tf(x));
}

__device__ __forceinline__ float ex2(float x) {
    float r;
    asm("ex2.approx.f32 %0, %1;" : "=f"(r) : "f"(x));
    return r;
}

__device__ __forceinline__ void mma8(float (&d)[4], const uint32_t (&a)[4],
                                     const uint32_t (&b)[2]) {
    asm volatile(
        "mma.sync.aligned.m16n8k8.row.col.f32.tf32.tf32.f32 "
        "{%0,%1,%2,%3},{%4,%5,%6,%7},{%8,%9},{%0,%1,%2,%3};"
        : "+f"(d[0]), "+f"(d[1]), "+f"(d[2]), "+f"(d[3])
        : "r"(a[0]), "r"(a[1]), "r"(a[2]), "r"(a[3]), "r"(b[0]), "r"(b[1]));
}

__device__ __forceinline__ uint32_t s2u(const void* p) {
    return (uint32_t)__cvta_generic_to_shared(p);
}

__device__ __forceinline__ void cpa16(uint32_t dst, const void* src) {
    asm volatile("cp.async.cg.shared.global [%0], [%1], 16;" :: "r"(dst), "l"(src));
}

#define CP_COMMIT() asm volatile("cp.async.commit_group;")
#define CP_WAIT0()  asm volatile("cp.async.wait_group 0;")

// ---------------------------------------------------------------------------
// lambda = exp(sum(lq1*lk1)) - exp(sum(lq2*lk2)) + LAMBDA_INIT
// ---------------------------------------------------------------------------
__global__ void lam_kernel(const float* __restrict__ lq1, const float* __restrict__ lk1,
                           const float* __restrict__ lq2, const float* __restrict__ lk2) {
    int i = threadIdx.x;  // 32 threads
    float p1 = lq1[i] * lk1[i];
    float p2 = lq2[i] * lk2[i];
    #pragma unroll
    for (int o = 16; o > 0; o >>= 1) {
        p1 += __shfl_xor_sync(0xffffffffu, p1, o);
        p2 += __shfl_xor_sync(0xffffffffu, p2, o);
    }
    if (i == 0) g_lam = expf(p1) - expf(p2) + LAMBDA_INIT_F;
}

// ---------------------------------------------------------------------------
// Prepass: round all GEMM operands (3 inputs + 4 weights) to tf32 in gmem.
// Grid (512, 1, 7), 256 threads, grid-stride over float4s per segment.
// ---------------------------------------------------------------------------
#define N4_IN  ((BC * NQC * DIMC) / 4)   // 1048576
#define N4_W   ((DIMC * DIMC) / 4)       // 262144

__global__ __launch_bounds__(256) void prepass_kernel(
    const float* __restrict__ q_in, const float* __restrict__ k_in,
    const float* __restrict__ v_in,
    const float* __restrict__ Wq, const float* __restrict__ Wk,
    const float* __restrict__ Wv, const float* __restrict__ Wp) {
    const int z = blockIdx.z;
    const float* src;
    float* dst;
    int n4;
    switch (z) {
        case 0:  src = q_in; dst = g_rq;  n4 = N4_IN; break;
        case 1:  src = k_in; dst = g_rk;  n4 = N4_IN; break;
        case 2:  src = v_in; dst = g_rv;  n4 = N4_IN; break;
        case 3:  src = Wq;   dst = g_rWq; n4 = N4_W;  break;
        case 4:  src = Wk;   dst = g_rWk; n4 = N4_W;  break;
        case 5:  src = Wv;   dst = g_rWv; n4 = N4_W;  break;
        default: src = Wp;   dst = g_rWp; n4 = N4_W;  break;
    }
    const int stride = gridDim.x * blockDim.x;
    for (int i = blockIdx.x * blockDim.x + threadIdx.x; i < n4; i += stride) {
        float4 v = ((const float4*)src)[i];
        v.x = f2tff(v.x); v.y = f2tff(v.y);
        v.z = f2tff(v.z); v.w = f2tff(v.w);
        ((float4*)dst)[i] = v;
    }
}

// ---------------------------------------------------------------------------
// tf32 GEMM core: operands PRE-ROUNDED in gmem — zero cvt in kernel.
// C[M,N] = A[M,K] @ B[N,K]^T (+ bias), 128x128 block, 8 warps (2x4),
// warp tile 64x32, kb=32, single smem buffer pitch 36, reg-prefetch pipeline.
// CVT_OUT rounds outputs (for qkv path feeding attention).
// ---------------------------------------------------------------------------
template <bool CVT_OUT>
__device__ __forceinline__ void gemm_body(const float* __restrict__ A,
                                          const float* __restrict__ B,
                                          const float* __restrict__ bias,
                                          float* __restrict__ C,
                                          int M, int N, int K,
                                          int bx, int by) {
    __shared__ float As[128][36];
    __shared__ float Bs[128][36];

    const int tid  = threadIdx.x;
    const int w    = tid >> 5;
    const int lane = tid & 31;
    const int gid  = lane >> 2;
    const int t    = lane & 3;
    const int wm   = w & 1;
    const int wn   = w >> 1;

    const int brow = by * 128;
    const int bcol = bx * 128;
    const float* Ag = A + (size_t)brow * K;
    const float* Bg = B + (size_t)bcol * K;

    float acc[4][4][4];
    #pragma unroll
    for (int mt = 0; mt < 4; mt++)
        #pragma unroll
        for (int nt = 0; nt < 4; nt++)
            #pragma unroll
            for (int r = 0; r < 4; r++) acc[mt][nt][r] = 0.0f;

    float4 av[4], bv[4];
    #pragma unroll
    for (int i = 0; i < 4; i++) {
        int c   = tid + 256 * i;
        int row = c >> 3;
        int d4  = (c & 7) * 4;
        av[i] = *(const float4*)(Ag + (size_t)row * K + d4);
        bv[i] = *(const float4*)(Bg + (size_t)row * K + d4);
    }

    const int NIT = K / 32;
    for (int it = 0; it < NIT; it++) {
        __syncthreads();
        #pragma unroll
        for (int i = 0; i < 4; i++) {
            int c   = tid + 256 * i;
            int row = c >> 3;
            int d4  = (c & 7) * 4;
            *(float4*)&As[row][d4] = av[i];
            *(float4*)&Bs[row][d4] = bv[i];
        }
        __syncthreads();

        if (it + 1 < NIT) {
            int kb = (it + 1) * 32;
            #pragma unroll
            for (int i = 0; i < 4; i++) {
                int c   = tid + 256 * i;
                int row = c >> 3;
                int d4  = (c & 7) * 4;
                av[i] = *(const float4*)(Ag + (size_t)row * K + kb + d4);
                bv[i] = *(const float4*)(Bg + (size_t)row * K + kb + d4);
            }
        }

        #pragma unroll
        for (int k = 0; k < 4; k++) {
            uint32_t af[4][4];
            uint32_t bf[4][2];
            #pragma unroll
            for (int mt = 0; mt < 4; mt++) {
                int r = wm * 64 + mt * 16;
                af[mt][0] = __float_as_uint(As[r + gid][k * 8 + t]);
                af[mt][1] = __float_as_uint(As[r + gid + 8][k * 8 + t]);
                af[mt][2] = __float_as_uint(As[r + gid][k * 8 + t + 4]);
                af[mt][3] = __float_as_uint(As[r + gid + 8][k * 8 + t + 4]);
            }
            #pragma unroll
            for (int nt = 0; nt < 4; nt++) {
                int r = wn * 32 + nt * 8;
                bf[nt][0] = __float_as_uint(Bs[r + gid][k * 8 + t]);
                bf[nt][1] = __float_as_uint(Bs[r + gid][k * 8 + t + 4]);
            }
            #pragma unroll
            for (int mt = 0; mt < 4; mt++)
                #pragma unroll
                for (int nt = 0; nt < 4; nt++)
                    mma8(acc[mt][nt], af[mt], bf[nt]);
        }
    }

    #pragma unroll
    for (int mt = 0; mt < 4; mt++) {
        int row = brow + wm * 64 + mt * 16 + gid;
        #pragma unroll
        for (int nt = 0; nt < 4; nt++) {
            int col = bcol + wn * 32 + nt * 8 + 2 * t;
            float v0 = acc[mt][nt][0], v1 = acc[mt][nt][1];
            float v2 = acc[mt][nt][2], v3 = acc[mt][nt][3];
            if (bias) {
                float b0 = bias[col], b1 = bias[col + 1];
                v0 += b0; v1 += b1; v2 += b0; v3 += b1;
            }
            if (CVT_OUT) {
                v0 = f2tff(v0); v1 = f2tff(v1);
                v2 = f2tff(v2); v3 = f2tff(v3);
            }
            *(float2*)(C + (size_t)row * N + col)       = make_float2(v0, v1);
            *(float2*)(C + (size_t)(row + 8) * N + col) = make_float2(v2, v3);
        }
    }
}

__global__ __launch_bounds__(256) void qkv_gemm() {
    const float* A = (blockIdx.z == 0) ? g_rq  : (blockIdx.z == 1) ? g_rk  : g_rv;
    const float* B = (blockIdx.z == 0) ? g_rWq : (blockIdx.z == 1) ? g_rWk : g_rWv;
    float*       C = (blockIdx.z == 0) ? g_Q   : (blockIdx.z == 1) ? g_K   : g_V;
    gemm_body<true>(A, B, nullptr, C, BC * NQC, DIMC, DIMC, blockIdx.x, blockIdx.y);
}

__global__ __launch_bounds__(256) void out_gemm(const float* __restrict__ bias,
                                                float* __restrict__ C) {
    gemm_body<false>(g_A, g_rWp, bias, C, BC * NQC, DIMC, DIMC, blockIdx.x, blockIdx.y);
}

// ---------------------------------------------------------------------------
// Fused dual-stream flash attention (tf32 mma) + lambda + RMSNorm + subln
// Grid: (B*H=32, NQ/64=32), 256 threads = 8 warps. (Unchanged from R10.)
// Epilogue writes g_A pre-rounded to tf32 (identical values to out_gemm's
// former store-side rounding).
// ---------------------------------------------------------------------------
__global__ __launch_bounds__(256) void attn_kernel(const float* __restrict__ subw) {
    __shared__ float sma[2 * 4608];

    const int b   = blockIdx.x >> 4;
    const int h   = blockIdx.x & 15;
    const int q0  = blockIdx.y << 6;
    const int tid = threadIdx.x;
    const int w    = tid >> 5;
    const int lane = tid & 31;
    const int s    = w >> 2;          // stream 0/1
    const int qs   = (w & 3) << 4;    // q-slab base within 64
    const int gid  = lane >> 2;
    const int t    = lane & 3;
    const int sg   = (gid >> 1) + (gid & 1) * 4;  // permuted key column

    const float* Qb = g_Q + ((size_t)b * NQC + q0) * DIMC + h * HDC;
    const float* Kb = g_K + (size_t)b * NKC * DIMC + h * HDC;
    const float* Vb = g_V + (size_t)b * NKC * DIMC + h * D2C;

    // Q fragments (persist; pre-scaled by SCALE*log2e; g_Q already tf32)
    uint32_t aQ[4][4];
    {
        const float* qr0 = Qb + (size_t)(qs + gid) * DIMC + s * (HC * HDC);
        const float* qr1 = qr0 + (size_t)8 * DIMC;
        #pragma unroll
        for (int k = 0; k < 4; k++) {
            aQ[k][0] = f2tf(qr0[k * 8 + t] * SCALE_L2E_F);
            aQ[k][1] = f2tf(qr1[k * 8 + t] * SCALE_L2E_F);
            aQ[k][2] = f2tf(qr0[k * 8 + t + 4] * SCALE_L2E_F);
            aQ[k][3] = f2tf(qr1[k * 8 + t + 4] * SCALE_L2E_F);
        }
    }

    float lacc0 = 0.0f, lacc1 = 0.0f;   // per-thread l partials
    float O[8][4];
    #pragma unroll
    for (int n = 0; n < 8; n++)
        #pragma unroll
        for (int r = 0; r < 4; r++) O[n][r] = 0.0f;

    // async tile prefetch: 1024 16B chunks (512 K + 512 V), 4 per thread
    auto prefetch = [&](int k0, int st) {
        float* base = sma + st * 4608;
        #pragma unroll
        for (int i = 0; i < 4; i++) {
            int c = tid + 256 * i;
            if (c < 512) {
                int str = c >> 8;
                int key = (c >> 3) & 31;
                int d4  = (c & 7) * 4;
                cpa16(s2u(base + str * 1152 + key * 36 + d4),
                      Kb + (size_t)(k0 + key) * DIMC + str * (HC * HDC) + d4);
            } else {
                int cc  = c - 512;
                int key = cc >> 4;
                int d4  = (cc & 15) * 4;
                cpa16(s2u(base + 2304 + key * 72 + d4),
                      Vb + (size_t)(k0 + key) * DIMC + d4);
            }
        }
    };

    prefetch(0, 0);
    CP_COMMIT();

    const int NIT = NKC / 32;  // 64
    for (int kt = 0; kt < NIT; kt++) {
        const int cur = kt & 1;
        CP_WAIT0();        // stage cur arrived
        __syncthreads();   // visible to all; all done with stage cur^1
        if (kt + 1 < NIT) {
            prefetch((kt + 1) * 32, cur ^ 1);
            CP_COMMIT();
        }

        const float* sKs = sma + cur * 4608 + s * 1152;      // [32][36]
        const float* sV  = sma + cur * 4608 + 2304;          // [32][72]

        // S = Q(16x32) x K^T (key columns permuted by sg within each 8-tile)
        float S[4][4];
        #pragma unroll
        for (int n = 0; n < 4; n++)
            #pragma unroll
            for (int r = 0; r < 4; r++) S[n][r] = 0.0f;

        #pragma unroll
        for (int k = 0; k < 4; k++) {
            #pragma unroll
            for (int n = 0; n < 4; n++) {
                uint32_t bf[2];
                bf[0] = __float_as_uint(sKs[(n * 8 + sg) * 36 + k * 8 + t]);
                bf[1] = __float_as_uint(sKs[(n * 8 + sg) * 36 + k * 8 + t + 4]);
                mma8(S[n], aQ[k], bf);
            }
        }

        // exp (no max subtraction), accumulate l partials, build A-frags
        uint32_t ap[4][4];
        #pragma unroll
        for (int n = 0; n < 4; n++) {
            float p0 = ex2(S[n][0]);
            float p1 = ex2(S[n][1]);
            float p2 = ex2(S[n][2]);
            float p3 = ex2(S[n][3]);
            lacc0 += p0 + p1;
            lacc1 += p2 + p3;
            ap[n][0] = f2tf(p0);
            ap[n][1] = f2tf(p2);
            ap[n][2] = f2tf(p1);
            ap[n][3] = f2tf(p3);
        }

        // O += P(16x32) x V(32x64)
        #pragma unroll
        for (int k = 0; k < 4; k++) {
            #pragma unroll
            for (int n = 0; n < 8; n++) {
                uint32_t bf[2];
                bf[0] = __float_as_uint(sV[(k * 8 + t) * 72 + n * 8 + gid]);
                bf[1] = __float_as_uint(sV[(k * 8 + t + 4) * 72 + n * 8 + gid]);
                mma8(O[n], ap[k], bf);
            }
        }
    }

    // final l reduction across the quad
    lacc0 += __shfl_xor_sync(0xffffffffu, lacc0, 1);
    lacc0 += __shfl_xor_sync(0xffffffffu, lacc0, 2);
    lacc1 += __shfl_xor_sync(0xffffffffu, lacc1, 1);
    lacc1 += __shfl_xor_sync(0xffffffffu, lacc1, 2);

    // ---------------- epilogue ----------------
    __syncthreads();  // mainloop done; overlay sX on stage memory

    float* sX = sma;  // [64][68] overlay (4352 <= 4608 floats)
    const float invl0 = 1.0f / lacc0;
    const float invl1 = 1.0f / lacc1;

    if (s == 1) {
        #pragma unroll
        for (int n = 0; n < 8; n++) {
            int c0 = n * 8 + 2 * t;
            *(float2*)&sX[(qs + gid) * 68 + c0] =
                make_float2(O[n][0] * invl0, O[n][1] * invl0);
            *(float2*)&sX[(qs + gid + 8) * 68 + c0] =
                make_float2(O[n][2] * invl1, O[n][3] * invl1);
        }
    }
    __syncthreads();

    if (s == 0) {
        const float lam = g_lam;
        float out[8][4];
        float ss0 = 0.0f, ss1 = 0.0f;
        #pragma unroll
        for (int n = 0; n < 8; n++) {
            int c0 = n * 8 + 2 * t;
            float2 x0 = *(float2*)&sX[(qs + gid) * 68 + c0];
            float2 x1 = *(float2*)&sX[(qs + gid + 8) * 68 + c0];
            out[n][0] = O[n][0] * invl0 - lam * x0.x;
            out[n][1] = O[n][1] * invl0 - lam * x0.y;
            out[n][2] = O[n][2] * invl1 - lam * x1.x;
            out[n][3] = O[n][3] * invl1 - lam * x1.y;
            ss0 += out[n][0] * out[n][0] + out[n][1] * out[n][1];
            ss1 += out[n][2] * out[n][2] + out[n][3] * out[n][3];
        }
        ss0 += __shfl_xor_sync(0xffffffffu, ss0, 1);
        ss0 += __shfl_xor_sync(0xffffffffu, ss0, 2);
        ss1 += __shfl_xor_sync(0xffffffffu, ss1, 1);
        ss1 += __shfl_xor_sync(0xffffffffu, ss1, 2);
        float r0 = rsqrtf(ss0 * (1.0f / 64.0f) + EPS_F);
        float r1 = rsqrtf(ss1 * (1.0f / 64.0f) + EPS_F);

        float* d0 = g_A + ((size_t)b * NQC + q0 + qs + gid) * DIMC + h * D2C;
        float* d1 = d0 + (size_t)8 * DIMC;
        #pragma unroll
        for (int n = 0; n < 8; n++) {
            int c0 = n * 8 + 2 * t;
            float w0 = subw[c0] * ONE_MINUS_LAMBDA_F;
            float w1 = subw[c0 + 1] * ONE_MINUS_LAMBDA_F;
            *(float2*)(d0 + c0) = make_float2(f2tff(out[n][0] * r0 * w0),
                                              f2tff(out[n][1] * r0 * w1));
            *(float2*)(d1 + c0) = make_float2(f2tff(out[n][2] * r1 * w0),
                                              f2tff(out[n][3] * r1 * w1));
        }
    }
}

// ---------------------------------------------------------------------------
extern "C" void kernel_launch(void* const* d_in, const int* in_sizes, int n_in,
                              void* d_out, int out_size) {
    const float* query = (const float*)d_in[0];
    const float* key_  = (const float*)d_in[1];
    const float* value = (const float*)d_in[2];
    const float* Wq    = (const float*)d_in[3];
    const float* Wk    = (const float*)d_in[4];
    const float* Wv    = (const float*)d_in[5];
    const float* Wp    = (const float*)d_in[6];
    const float* bp    = (const float*)d_in[7];
    const float* lq1   = (const float*)d_in[8];
    const float* lk1   = (const float*)d_in[9];
    const float* lq2   = (const float*)d_in[10];
    const float* lk2   = (const float*)d_in[11];
    const float* subw  = (const float*)d_in[12];
    float* out = (float*)d_out;

    lam_kernel<<<1, 32>>>(lq1, lk1, lq2, lk2);

    dim3 pgrid(512, 1, 7);
    prepass_kernel<<<pgrid, 256>>>(query, key_, value, Wq, Wk, Wv, Wp);

    dim3 qkvgrid(DIMC / 128, (BC * NQC) / 128, 3);  // (8, 32, 3)
    qkv_gemm<<<qkvgrid, 256>>>();

    dim3 agrid(BC * HC, NQC / 64);  // (32, 32)
    attn_kernel<<<agrid, 256>>>(subw);

    dim3 ogrid(DIMC / 128, (BC * NQC) / 128);  // (8, 32)
    out_gemm<<<ogrid, 256>>>(bp, out);
}

// round 13
// speedup vs baseline: 1.0378x; 1.0378x over previous
#include <cuda_runtime.h>
#include <cstdint>

// Problem constants
#define BC    2
#define NQC   2048
#define NKC   2048
#define DIMC  1024
#define HC    16
#define HDC   32
#define D2C   64
#define LAMBDA_INIT_F 0.6192834728526787f
#define ONE_MINUS_LAMBDA_F 0.3807165271473213f
#define SCALE_F 0.17677669529663687f
#define SCALE_L2E_F (0.17677669529663687f * 1.44269504088896340f)
#define EPS_F 1e-5f

// Scratch (device globals — no runtime allocation allowed)
__device__ float g_Q[(size_t)BC * NQC * DIMC];
__device__ float g_K[(size_t)BC * NKC * DIMC];
__device__ float g_V[(size_t)BC * NKC * DIMC];
__device__ float g_A[(size_t)BC * NQC * DIMC];
// tf32-rounded operand copies (prepass output)
__device__ float g_rq[(size_t)BC * NQC * DIMC];
__device__ float g_rk[(size_t)BC * NKC * DIMC];
__device__ float g_rv[(size_t)BC * NKC * DIMC];
__device__ float g_rWq[(size_t)DIMC * DIMC];
__device__ float g_rWk[(size_t)DIMC * DIMC];
__device__ float g_rWv[(size_t)DIMC * DIMC];
__device__ float g_rWp[(size_t)DIMC * DIMC];
__device__ float g_lam;

// ---------------------------------------------------------------------------
// helpers
// ---------------------------------------------------------------------------
__device__ __forceinline__ uint32_t f2tf(float x) {
    uint32_t u;
    asm("cvt.rna.tf32.f32 %0, %1;" : "=r"(u) : "f"(x));
    return u;
}
__device__ __forceinline__ float f2tff(float x) {
    return __uint_as_float(f2tf(x));
}

__device__ __forceinline__ float ex2(float x) {
    float r;
    asm("ex2.approx.f32 %0, %1;" : "=f"(r) : "f"(x));
    return r;
}

__device__ __forceinline__ void mma8(float (&d)[4], const uint32_t (&a)[4],
                                     const uint32_t (&b)[2]) {
    asm volatile(
        "mma.sync.aligned.m16n8k8.row.col.f32.tf32.tf32.f32 "
        "{%0,%1,%2,%3},{%4,%5,%6,%7},{%8,%9},{%0,%1,%2,%3};"
        : "+f"(d[0]), "+f"(d[1]), "+f"(d[2]), "+f"(d[3])
        : "r"(a[0]), "r"(a[1]), "r"(a[2]), "r"(a[3]), "r"(b[0]), "r"(b[1]));
}

__device__ __forceinline__ uint32_t s2u(const void* p) {
    return (uint32_t)__cvta_generic_to_shared(p);
}

__device__ __forceinline__ void cpa16(uint32_t dst, const void* src) {
    asm volatile("cp.async.cg.shared.global [%0], [%1], 16;" :: "r"(dst), "l"(src));
}

#define CP_COMMIT() asm volatile("cp.async.commit_group;")
#define CP_WAIT0()  asm volatile("cp.async.wait_group 0;")

// ---------------------------------------------------------------------------
// lambda = exp(sum(lq1*lk1)) - exp(sum(lq2*lk2)) + LAMBDA_INIT
// ---------------------------------------------------------------------------
__global__ void lam_kernel(const float* __restrict__ lq1, const float* __restrict__ lk1,
                           const float* __restrict__ lq2, const float* __restrict__ lk2) {
    int i = threadIdx.x;  // 32 threads
    float p1 = lq1[i] * lk1[i];
    float p2 = lq2[i] * lk2[i];
    #pragma unroll
    for (int o = 16; o > 0; o >>= 1) {
        p1 += __shfl_xor_sync(0xffffffffu, p1, o);
        p2 += __shfl_xor_sync(0xffffffffu, p2, o);
    }
    if (i == 0) g_lam = expf(p1) - expf(p2) + LAMBDA_INIT_F;
}

// ---------------------------------------------------------------------------
// Prepass: round all GEMM operands (3 inputs + 4 weights) to tf32 in gmem.
// ---------------------------------------------------------------------------
#define N4_IN  ((BC * NQC * DIMC) / 4)   // 1048576
#define N4_W   ((DIMC * DIMC) / 4)       // 262144

__global__ __launch_bounds__(256) void prepass_kernel(
    const float* __restrict__ q_in, const float* __restrict__ k_in,
    const float* __restrict__ v_in,
    const float* __restrict__ Wq, const float* __restrict__ Wk,
    const float* __restrict__ Wv, const float* __restrict__ Wp) {
    const int z = blockIdx.z;
    const float* src;
    float* dst;
    int n4;
    switch (z) {
        case 0:  src = q_in; dst = g_rq;  n4 = N4_IN; break;
        case 1:  src = k_in; dst = g_rk;  n4 = N4_IN; break;
        case 2:  src = v_in; dst = g_rv;  n4 = N4_IN; break;
        case 3:  src = Wq;   dst = g_rWq; n4 = N4_W;  break;
        case 4:  src = Wk;   dst = g_rWk; n4 = N4_W;  break;
        case 5:  src = Wv;   dst = g_rWv; n4 = N4_W;  break;
        default: src = Wp;   dst = g_rWp; n4 = N4_W;  break;
    }
    const int stride = gridDim.x * blockDim.x;
    for (int i = blockIdx.x * blockDim.x + threadIdx.x; i < n4; i += stride) {
        float4 v = ((const float4*)src)[i];
        v.x = f2tff(v.x); v.y = f2tff(v.y);
        v.z = f2tff(v.z); v.w = f2tff(v.w);
        ((float4*)dst)[i] = v;
    }
}

// ---------------------------------------------------------------------------
// tf32 GEMM core: operands PRE-ROUNDED in gmem — zero cvt in kernel.
// (unchanged from R11)
// ---------------------------------------------------------------------------
template <bool CVT_OUT>
__device__ __forceinline__ void gemm_body(const float* __restrict__ A,
                                          const float* __restrict__ B,
                                          const float* __restrict__ bias,
                                          float* __restrict__ C,
                                          int M, int N, int K,
                                          int bx, int by) {
    __shared__ float As[128][36];
    __shared__ float Bs[128][36];

    const int tid  = threadIdx.x;
    const int w    = tid >> 5;
    const int lane = tid & 31;
    const int gid  = lane >> 2;
    const int t    = lane & 3;
    const int wm   = w & 1;
    const int wn   = w >> 1;

    const int brow = by * 128;
    const int bcol = bx * 128;
    const float* Ag = A + (size_t)brow * K;
    const float* Bg = B + (size_t)bcol * K;

    float acc[4][4][4];
    #pragma unroll
    for (int mt = 0; mt < 4; mt++)
        #pragma unroll
        for (int nt = 0; nt < 4; nt++)
            #pragma unroll
            for (int r = 0; r < 4; r++) acc[mt][nt][r] = 0.0f;

    float4 av[4], bv[4];
    #pragma unroll
    for (int i = 0; i < 4; i++) {
        int c   = tid + 256 * i;
        int row = c >> 3;
        int d4  = (c & 7) * 4;
        av[i] = *(const float4*)(Ag + (size_t)row * K + d4);
        bv[i] = *(const float4*)(Bg + (size_t)row * K + d4);
    }

    const int NIT = K / 32;
    for (int it = 0; it < NIT; it++) {
        __syncthreads();
        #pragma unroll
        for (int i = 0; i < 4; i++) {
            int c   = tid + 256 * i;
            int row = c >> 3;
            int d4  = (c & 7) * 4;
            *(float4*)&As[row][d4] = av[i];
            *(float4*)&Bs[row][d4] = bv[i];
        }
        __syncthreads();

        if (it + 1 < NIT) {
            int kb = (it + 1) * 32;
            #pragma unroll
            for (int i = 0; i < 4; i++) {
                int c   = tid + 256 * i;
                int row = c >> 3;
                int d4  = (c & 7) * 4;
                av[i] = *(const float4*)(Ag + (size_t)row * K + kb + d4);
                bv[i] = *(const float4*)(Bg + (size_t)row * K + kb + d4);
            }
        }

        #pragma unroll
        for (int k = 0; k < 4; k++) {
            uint32_t af[4][4];
            uint32_t bf[4][2];
            #pragma unroll
            for (int mt = 0; mt < 4; mt++) {
                int r = wm * 64 + mt * 16;
                af[mt][0] = __float_as_uint(As[r + gid][k * 8 + t]);
                af[mt][1] = __float_as_uint(As[r + gid + 8][k * 8 + t]);
                af[mt][2] = __float_as_uint(As[r + gid][k * 8 + t + 4]);
                af[mt][3] = __float_as_uint(As[r + gid + 8][k * 8 + t + 4]);
            }
            #pragma unroll
            for (int nt = 0; nt < 4; nt++) {
                int r = wn * 32 + nt * 8;
                bf[nt][0] = __float_as_uint(Bs[r + gid][k * 8 + t]);
                bf[nt][1] = __float_as_uint(Bs[r + gid][k * 8 + t + 4]);
            }
            #pragma unroll
            for (int mt = 0; mt < 4; mt++)
                #pragma unroll
                for (int nt = 0; nt < 4; nt++)
                    mma8(acc[mt][nt], af[mt], bf[nt]);
        }
    }

    #pragma unroll
    for (int mt = 0; mt < 4; mt++) {
        int row = brow + wm * 64 + mt * 16 + gid;
        #pragma unroll
        for (int nt = 0; nt < 4; nt++) {
            int col = bcol + wn * 32 + nt * 8 + 2 * t;
            float v0 = acc[mt][nt][0], v1 = acc[mt][nt][1];
            float v2 = acc[mt][nt][2], v3 = acc[mt][nt][3];
            if (bias) {
                float b0 = bias[col], b1 = bias[col + 1];
                v0 += b0; v1 += b1; v2 += b0; v3 += b1;
            }
            if (CVT_OUT) {
                v0 = f2tff(v0); v1 = f2tff(v1);
                v2 = f2tff(v2); v3 = f2tff(v3);
            }
            *(float2*)(C + (size_t)row * N + col)       = make_float2(v0, v1);
            *(float2*)(C + (size_t)(row + 8) * N + col) = make_float2(v2, v3);
        }
    }
}

__global__ __launch_bounds__(256) void qkv_gemm() {
    const float* A = (blockIdx.z == 0) ? g_rq  : (blockIdx.z == 1) ? g_rk  : g_rv;
    const float* B = (blockIdx.z == 0) ? g_rWq : (blockIdx.z == 1) ? g_rWk : g_rWv;
    float*       C = (blockIdx.z == 0) ? g_Q   : (blockIdx.z == 1) ? g_K   : g_V;
    gemm_body<true>(A, B, nullptr, C, BC * NQC, DIMC, DIMC, blockIdx.x, blockIdx.y);
}

__global__ __launch_bounds__(256) void out_gemm(const float* __restrict__ bias,
                                                float* __restrict__ C) {
    gemm_body<false>(g_A, g_rWp, bias, C, BC * NQC, DIMC, DIMC, blockIdx.x, blockIdx.y);
}

// ---------------------------------------------------------------------------
// Fused dual-stream flash attention — BOTH streams per warp (V-frag sharing).
// Grid: (B*H=32, NQ/64=32), 128 threads = 4 warps; warp w handles q-rows
// [qs, qs+16) for BOTH differential streams. One V-fragment load feeds both
// streams' PV mma: smem reads drop from 375B/mma to 250B/mma (crossbar is
// the measured bottleneck, L1=58.4%). Epilogue is warp-local (no exchange).
// K-tile = 32; cp.async double-buffered; no online max (scores O(10));
// key-permutation keeps P in registers.
// Static smem: stages[2][4608] floats = 36864 B.
// ---------------------------------------------------------------------------
__global__ __launch_bounds__(128) void attn_kernel(const float* __restrict__ subw) {
    __shared__ float sma[2 * 4608];

    const int b   = blockIdx.x >> 4;
    const int h   = blockIdx.x & 15;
    const int q0  = blockIdx.y << 6;
    const int tid = threadIdx.x;
    const int w    = tid >> 5;
    const int lane = tid & 31;
    const int qs   = w << 4;          // q-slab base within 64
    const int gid  = lane >> 2;
    const int t    = lane & 3;
    const int sg   = (gid >> 1) + (gid & 1) * 4;  // permuted key column

    const float* Qb = g_Q + ((size_t)b * NQC + q0 + qs) * DIMC + h * HDC;
    const float* Kb = g_K + (size_t)b * NKC * DIMC + h * HDC;
    const float* Vb = g_V + (size_t)b * NKC * DIMC + h * D2C;

    // Q fragments, both streams (persist; pre-scaled by SCALE*log2e)
    uint32_t aQ[2][4][4];
    #pragma unroll
    for (int s = 0; s < 2; s++) {
        const float* qr0 = Qb + (size_t)gid * DIMC + s * (HC * HDC);
        const float* qr1 = qr0 + (size_t)8 * DIMC;
        #pragma unroll
        for (int k = 0; k < 4; k++) {
            aQ[s][k][0] = f2tf(qr0[k * 8 + t] * SCALE_L2E_F);
            aQ[s][k][1] = f2tf(qr1[k * 8 + t] * SCALE_L2E_F);
            aQ[s][k][2] = f2tf(qr0[k * 8 + t + 4] * SCALE_L2E_F);
            aQ[s][k][3] = f2tf(qr1[k * 8 + t + 4] * SCALE_L2E_F);
        }
    }

    float lacc[2][2] = {{0.0f, 0.0f}, {0.0f, 0.0f}};
    float O[2][8][4];
    #pragma unroll
    for (int s = 0; s < 2; s++)
        #pragma unroll
        for (int n = 0; n < 8; n++)
            #pragma unroll
            for (int r = 0; r < 4; r++) O[s][n][r] = 0.0f;

    // async tile prefetch: 1024 16B chunks (512 K + 512 V), 8 per thread
    auto prefetch = [&](int k0, int st) {
        float* base = sma + st * 4608;
        #pragma unroll
        for (int i = 0; i < 8; i++) {
            int c = tid + 128 * i;
            if (c < 512) {
                int str = c >> 8;
                int key = (c >> 3) & 31;
                int d4  = (c & 7) * 4;
                cpa16(s2u(base + str * 1152 + key * 36 + d4),
                      Kb + (size_t)(k0 + key) * DIMC + str * (HC * HDC) + d4);
            } else {
                int cc  = c - 512;
                int key = cc >> 4;
                int d4  = (cc & 15) * 4;
                cpa16(s2u(base + 2304 + key * 72 + d4),
                      Vb + (size_t)(k0 + key) * DIMC + d4);
            }
        }
    };

    prefetch(0, 0);
    CP_COMMIT();

    const int NIT = NKC / 32;  // 64
    for (int kt = 0; kt < NIT; kt++) {
        const int cur = kt & 1;
        CP_WAIT0();        // stage cur arrived
        __syncthreads();   // visible to all; all done with stage cur^1
        if (kt + 1 < NIT) {
            prefetch((kt + 1) * 32, cur ^ 1);
            CP_COMMIT();
        }

        const float* sK0 = sma + cur * 4608;                 // stream0 K [32][36]
        const float* sK1 = sK0 + 1152;                       // stream1 K
        const float* sV  = sma + cur * 4608 + 2304;          // V [32][72]

        // S[s] = Q[s](16x32) x K[s]^T (key columns permuted by sg)
        float S[2][4][4];
        #pragma unroll
        for (int s = 0; s < 2; s++)
            #pragma unroll
            for (int n = 0; n < 4; n++)
                #pragma unroll
                for (int r = 0; r < 4; r++) S[s][n][r] = 0.0f;

        #pragma unroll
        for (int k = 0; k < 4; k++) {
            #pragma unroll
            for (int n = 0; n < 4; n++) {
                uint32_t bf0[2], bf1[2];
                bf0[0] = __float_as_uint(sK0[(n * 8 + sg) * 36 + k * 8 + t]);
                bf0[1] = __float_as_uint(sK0[(n * 8 + sg) * 36 + k * 8 + t + 4]);
                bf1[0] = __float_as_uint(sK1[(n * 8 + sg) * 36 + k * 8 + t]);
                bf1[1] = __float_as_uint(sK1[(n * 8 + sg) * 36 + k * 8 + t + 4]);
                mma8(S[0][n], aQ[0][k], bf0);
                mma8(S[1][n], aQ[1][k], bf1);
            }
        }

        // exp (no max), accumulate l partials, build A-frags in place
        uint32_t ap[2][4][4];
        #pragma unroll
        for (int s = 0; s < 2; s++) {
            #pragma unroll
            for (int n = 0; n < 4; n++) {
                float p0 = ex2(S[s][n][0]);
                float p1 = ex2(S[s][n][1]);
                float p2 = ex2(S[s][n][2]);
                float p3 = ex2(S[s][n][3]);
                lacc[s][0] += p0 + p1;
                lacc[s][1] += p2 + p3;
                ap[s][n][0] = f2tf(p0);
                ap[s][n][1] = f2tf(p2);
                ap[s][n][2] = f2tf(p1);
                ap[s][n][3] = f2tf(p3);
            }
        }

        // O[s] += P[s](16x32) x V(32x64) — ONE V-frag load serves both streams
        #pragma unroll
        for (int k = 0; k < 4; k++) {
            #pragma unroll
            for (int n = 0; n < 8; n++) {
                uint32_t bf[2];
                bf[0] = __float_as_uint(sV[(k * 8 + t) * 72 + n * 8 + gid]);
                bf[1] = __float_as_uint(sV[(k * 8 + t + 4) * 72 + n * 8 + gid]);
                mma8(O[0][n], ap[0][k], bf);
                mma8(O[1][n], ap[1][k], bf);
            }
        }
    }

    // final l reductions across the quad
    #pragma unroll
    for (int s = 0; s < 2; s++) {
        lacc[s][0] += __shfl_xor_sync(0xffffffffu, lacc[s][0], 1);
        lacc[s][0] += __shfl_xor_sync(0xffffffffu, lacc[s][0], 2);
        lacc[s][1] += __shfl_xor_sync(0xffffffffu, lacc[s][1], 1);
        lacc[s][1] += __shfl_xor_sync(0xffffffffu, lacc[s][1], 2);
    }

    // ---------------- epilogue (fully warp-local) ----------------
    const float lam = g_lam;
    const float i00 = 1.0f / lacc[0][0];
    const float i01 = 1.0f / lacc[0][1];
    const float i10 = lam / lacc[1][0];
    const float i11 = lam / lacc[1][1];

    float out[8][4];
    float ss0 = 0.0f, ss1 = 0.0f;
    #pragma unroll
    for (int n = 0; n < 8; n++) {
        out[n][0] = O[0][n][0] * i00 - O[1][n][0] * i10;
        out[n][1] = O[0][n][1] * i00 - O[1][n][1] * i10;
        out[n][2] = O[0][n][2] * i01 - O[1][n][2] * i11;
        out[n][3] = O[0][n][3] * i01 - O[1][n][3] * i11;
        ss0 += out[n][0] * out[n][0] + out[n][1] * out[n][1];
        ss1 += out[n][2] * out[n][2] + out[n][3] * out[n][3];
    }
    ss0 += __shfl_xor_sync(0xffffffffu, ss0, 1);
    ss0 += __shfl_xor_sync(0xffffffffu, ss0, 2);
    ss1 += __shfl_xor_sync(0xffffffffu, ss1, 1);
    ss1 += __shfl_xor_sync(0xffffffffu, ss1, 2);
    float r0 = rsqrtf(ss0 * (1.0f / 64.0f) + EPS_F);
    float r1 = rsqrtf(ss1 * (1.0f / 64.0f) + EPS_F);

    float* d0 = g_A + ((size_t)b * NQC + q0 + qs + gid) * DIMC + h * D2C;
    float* d1 = d0 + (size_t)8 * DIMC;
    #pragma unroll
    for (int n = 0; n < 8; n++) {
        int c0 = n * 8 + 2 * t;
        float w0 = subw[c0] * ONE_MINUS_LAMBDA_F;
        float w1 = subw[c0 + 1] * ONE_MINUS_LAMBDA_F;
        *(float2*)(d0 + c0) = make_float2(f2tff(out[n][0] * r0 * w0),
                                          f2tff(out[n][1] * r0 * w1));
        *(float2*)(d1 + c0) = make_float2(f2tff(out[n][2] * r1 * w0),
                                          f2tff(out[n][3] * r1 * w1));
    }
}

// ---------------------------------------------------------------------------
extern "C" void kernel_launch(void* const* d_in, const int* in_sizes, int n_in,
                              void* d_out, int out_size) {
    const float* query = (const float*)d_in[0];
    const float* key_  = (const float*)d_in[1];
    const float* value = (const float*)d_in[2];
    const float* Wq    = (const float*)d_in[3];
    const float* Wk    = (const float*)d_in[4];
    const float* Wv    = (const float*)d_in[5];
    const float* Wp    = (const float*)d_in[6];
    const float* bp    = (const float*)d_in[7];
    const float* lq1   = (const float*)d_in[8];
    const float* lk1   = (const float*)d_in[9];
    const float* lq2   = (const float*)d_in[10];
    const float* lk2   = (const float*)d_in[11];
    const float* subw  = (const float*)d_in[12];
    float* out = (float*)d_out;

    lam_kernel<<<1, 32>>>(lq1, lk1, lq2, lk2);

    dim3 pgrid(512, 1, 7);
    prepass_kernel<<<pgrid, 256>>>(query, key_, value, Wq, Wk, Wv, Wp);

    dim3 qkvgrid(DIMC / 128, (BC * NQC) / 128, 3);  // (8, 32, 3)
    qkv_gemm<<<qkvgrid, 256>>>();

    dim3 agrid(BC * HC, NQC / 64);  // (32, 32)
    attn_kernel<<<agrid, 128>>>(subw);

    dim3 ogrid(DIMC / 128, (BC * NQC) / 128);  // (8, 32)
    out_gemm<<<ogrid, 256>>>(bp, out);
}

// round 14
// speedup vs baseline: 1.0519x; 1.0136x over previous
#include <cuda_runtime.h>
#include <cstdint>

// Problem constants
#define BC    2
#define NQC   2048
#define NKC   2048
#define DIMC  1024
#define HC    16
#define HDC   32
#define D2C   64
#define LAMBDA_INIT_F 0.6192834728526787f
#define ONE_MINUS_LAMBDA_F 0.3807165271473213f
#define SCALE_F 0.17677669529663687f
#define SCALE_L2E_F (0.17677669529663687f * 1.44269504088896340f)
#define EPS_F 1e-5f

// Scratch (device globals — no runtime allocation allowed)
__device__ float g_Q[(size_t)BC * NQC * DIMC];
__device__ float g_K[(size_t)BC * NKC * DIMC];
__device__ float g_V[(size_t)BC * NKC * DIMC];
__device__ float g_A[(size_t)BC * NQC * DIMC];
// tf32-rounded operand copies (prepass output)
__device__ float g_rq[(size_t)BC * NQC * DIMC];
__device__ float g_rk[(size_t)BC * NKC * DIMC];
__device__ float g_rv[(size_t)BC * NKC * DIMC];
__device__ float g_rWq[(size_t)DIMC * DIMC];
__device__ float g_rWk[(size_t)DIMC * DIMC];
__device__ float g_rWv[(size_t)DIMC * DIMC];
__device__ float g_rWp[(size_t)DIMC * DIMC];
__device__ float g_lam;

// ---------------------------------------------------------------------------
// helpers
// ---------------------------------------------------------------------------
__device__ __forceinline__ uint32_t f2tf(float x) {
    uint32_t u;
    asm("cvt.rna.tf32.f32 %0, %1;" : "=r"(u) : "f"(x));
    return u;
}
__device__ __forceinline__ float f2tff(float x) {
    return __uint_as_float(f2tf(x));
}

__device__ __forceinline__ float ex2(float x) {
    float r;
    asm("ex2.approx.f32 %0, %1;" : "=f"(r) : "f"(x));
    return r;
}

__device__ __forceinline__ void mma8(float (&d)[4], const uint32_t (&a)[4],
                                     const uint32_t (&b)[2]) {
    asm volatile(
        "mma.sync.aligned.m16n8k8.row.col.f32.tf32.tf32.f32 "
        "{%0,%1,%2,%3},{%4,%5,%6,%7},{%8,%9},{%0,%1,%2,%3};"
        : "+f"(d[0]), "+f"(d[1]), "+f"(d[2]), "+f"(d[3])
        : "r"(a[0]), "r"(a[1]), "r"(a[2]), "r"(a[3]), "r"(b[0]), "r"(b[1]));
}

__device__ __forceinline__ uint32_t s2u(const void* p) {
    return (uint32_t)__cvta_generic_to_shared(p);
}

__device__ __forceinline__ void cpa16(uint32_t dst, const void* src) {
    asm volatile("cp.async.cg.shared.global [%0], [%1], 16;" :: "r"(dst), "l"(src));
}

#define CP_COMMIT() asm volatile("cp.async.commit_group;")
#define CP_WAIT0()  asm volatile("cp.async.wait_group 0;")

// ---------------------------------------------------------------------------
// lambda = exp(sum(lq1*lk1)) - exp(sum(lq2*lk2)) + LAMBDA_INIT
// ---------------------------------------------------------------------------
__global__ void lam_kernel(const float* __restrict__ lq1, const float* __restrict__ lk1,
                           const float* __restrict__ lq2, const float* __restrict__ lk2) {
    int i = threadIdx.x;  // 32 threads
    float p1 = lq1[i] * lk1[i];
    float p2 = lq2[i] * lk2[i];
    #pragma unroll
    for (int o = 16; o > 0; o >>= 1) {
        p1 += __shfl_xor_sync(0xffffffffu, p1, o);
        p2 += __shfl_xor_sync(0xffffffffu, p2, o);
    }
    if (i == 0) g_lam = expf(p1) - expf(p2) + LAMBDA_INIT_F;
}

// ---------------------------------------------------------------------------
// Prepass: round all GEMM operands (3 inputs + 4 weights) to tf32 in gmem.
// ---------------------------------------------------------------------------
#define N4_IN  ((BC * NQC * DIMC) / 4)   // 1048576
#define N4_W   ((DIMC * DIMC) / 4)       // 262144

__global__ __launch_bounds__(256) void prepass_kernel(
    const float* __restrict__ q_in, const float* __restrict__ k_in,
    const float* __restrict__ v_in,
    const float* __restrict__ Wq, const float* __restrict__ Wk,
    const float* __restrict__ Wv, const float* __restrict__ Wp) {
    const int z = blockIdx.z;
    const float* src;
    float* dst;
    int n4;
    switch (z) {
        case 0:  src = q_in; dst = g_rq;  n4 = N4_IN; break;
        case 1:  src = k_in; dst = g_rk;  n4 = N4_IN; break;
        case 2:  src = v_in; dst = g_rv;  n4 = N4_IN; break;
        case 3:  src = Wq;   dst = g_rWq; n4 = N4_W;  break;
        case 4:  src = Wk;   dst = g_rWk; n4 = N4_W;  break;
        case 5:  src = Wv;   dst = g_rWv; n4 = N4_W;  break;
        default: src = Wp;   dst = g_rWp; n4 = N4_W;  break;
    }
    const int stride = gridDim.x * blockDim.x;
    for (int i = blockIdx.x * blockDim.x + threadIdx.x; i < n4; i += stride) {
        float4 v = ((const float4*)src)[i];
        v.x = f2tff(v.x); v.y = f2tff(v.y);
        v.z = f2tff(v.z); v.w = f2tff(v.w);
        ((float4*)dst)[i] = v;
    }
}

// ---------------------------------------------------------------------------
// tf32 GEMM core: cp.async double-buffered (clean now — operands pre-rounded,
// zero cvt, zero register staging). Pipeline skeleton mirrors attn_kernel's
// proven pattern: WAIT0 -> one __syncthreads -> prefetch other stage -> mma.
// C[M,N] = A[M,K] @ B[N,K]^T (+ bias), 128x128 block, 8 warps (2x4),
// warp tile 64x32, kb=32, pitch 36.
// Dynamic smem (floats): As[st] at st*4608, Bs[st] at 9216 + st*4608.
// Total 18432 floats = 73728 B -> 2 CTAs/SM (147KB < 228KB).
// ---------------------------------------------------------------------------
#define GEMM_SMEM_BYTES (18432 * 4)

template <bool CVT_OUT>
__device__ __forceinline__ void gemm_body(const float* __restrict__ A,
                                          const float* __restrict__ B,
                                          const float* __restrict__ bias,
                                          float* __restrict__ C,
                                          int M, int N, int K,
                                          int bx, int by) {
    extern __shared__ float smg[];

    const int tid  = threadIdx.x;
    const int w    = tid >> 5;
    const int lane = tid & 31;
    const int gid  = lane >> 2;
    const int t    = lane & 3;
    const int wm   = w & 1;
    const int wn   = w >> 1;

    const int brow = by * 128;
    const int bcol = bx * 128;
    const float* Ag = A + (size_t)brow * K;
    const float* Bg = B + (size_t)bcol * K;

    float acc[4][4][4];
    #pragma unroll
    for (int mt = 0; mt < 4; mt++)
        #pragma unroll
        for (int nt = 0; nt < 4; nt++)
            #pragma unroll
            for (int r = 0; r < 4; r++) acc[mt][nt][r] = 0.0f;

    // async prefetch of one k-block (32 cols): 4 A-chunks + 4 B-chunks/thread
    auto prefetch = [&](int kb, int st) {
        float* As = smg + st * 4608;
        float* Bs = smg + 9216 + st * 4608;
        #pragma unroll
        for (int i = 0; i < 4; i++) {
            int c   = tid + 256 * i;
            int row = c >> 3;
            int d4  = (c & 7) * 4;
            cpa16(s2u(As + row * 36 + d4), Ag + (size_t)row * K + kb + d4);
            cpa16(s2u(Bs + row * 36 + d4), Bg + (size_t)row * K + kb + d4);
        }
    };

    prefetch(0, 0);
    CP_COMMIT();

    const int NIT = K / 32;
    for (int it = 0; it < NIT; it++) {
        const int cur = it & 1;
        CP_WAIT0();        // stage cur arrived
        __syncthreads();   // visible to all; all done with stage cur^1
        if (it + 1 < NIT) {
            prefetch((it + 1) * 32, cur ^ 1);
            CP_COMMIT();
        }

        const float* As = smg + cur * 4608;
        const float* Bs = smg + 9216 + cur * 4608;

        #pragma unroll
        for (int k = 0; k < 4; k++) {
            uint32_t af[4][4];
            uint32_t bf[4][2];
            #pragma unroll
            for (int mt = 0; mt < 4; mt++) {
                int r = wm * 64 + mt * 16;
                af[mt][0] = __float_as_uint(As[(r + gid) * 36 + k * 8 + t]);
                af[mt][1] = __float_as_uint(As[(r + gid + 8) * 36 + k * 8 + t]);
                af[mt][2] = __float_as_uint(As[(r + gid) * 36 + k * 8 + t + 4]);
                af[mt][3] = __float_as_uint(As[(r + gid + 8) * 36 + k * 8 + t + 4]);
            }
            #pragma unroll
            for (int nt = 0; nt < 4; nt++) {
                int r = wn * 32 + nt * 8;
                bf[nt][0] = __float_as_uint(Bs[(r + gid) * 36 + k * 8 + t]);
                bf[nt][1] = __float_as_uint(Bs[(r + gid) * 36 + k * 8 + t + 4]);
            }
            #pragma unroll
            for (int mt = 0; mt < 4; mt++)
                #pragma unroll
                for (int nt = 0; nt < 4; nt++)
                    mma8(acc[mt][nt], af[mt], bf[nt]);
        }
    }

    #pragma unroll
    for (int mt = 0; mt < 4; mt++) {
        int row = brow + wm * 64 + mt * 16 + gid;
        #pragma unroll
        for (int nt = 0; nt < 4; nt++) {
            int col = bcol + wn * 32 + nt * 8 + 2 * t;
            float v0 = acc[mt][nt][0], v1 = acc[mt][nt][1];
            float v2 = acc[mt][nt][2], v3 = acc[mt][nt][3];
            if (bias) {
                float b0 = bias[col], b1 = bias[col + 1];
                v0 += b0; v1 += b1; v2 += b0; v3 += b1;
            }
            if (CVT_OUT) {
                v0 = f2tff(v0); v1 = f2tff(v1);
                v2 = f2tff(v2); v3 = f2tff(v3);
            }
            *(float2*)(C + (size_t)row * N + col)       = make_float2(v0, v1);
            *(float2*)(C + (size_t)(row + 8) * N + col) = make_float2(v2, v3);
        }
    }
}

__global__ __launch_bounds__(256, 2) void qkv_gemm() {
    const float* A = (blockIdx.z == 0) ? g_rq  : (blockIdx.z == 1) ? g_rk  : g_rv;
    const float* B = (blockIdx.z == 0) ? g_rWq : (blockIdx.z == 1) ? g_rWk : g_rWv;
    float*       C = (blockIdx.z == 0) ? g_Q   : (blockIdx.z == 1) ? g_K   : g_V;
    gemm_body<true>(A, B, nullptr, C, BC * NQC, DIMC, DIMC, blockIdx.x, blockIdx.y);
}

__global__ __launch_bounds__(256, 2) void out_gemm(const float* __restrict__ bias,
                                                   float* __restrict__ C) {
    gemm_body<false>(g_A, g_rWp, bias, C, BC * NQC, DIMC, DIMC, blockIdx.x, blockIdx.y);
}

// ---------------------------------------------------------------------------
// Fused dual-stream flash attention — BOTH streams per warp (V-frag sharing).
// (Unchanged from R13 — proven best.)
// ---------------------------------------------------------------------------
__global__ __launch_bounds__(128) void attn_kernel(const float* __restrict__ subw) {
    __shared__ float sma[2 * 4608];

    const int b   = blockIdx.x >> 4;
    const int h   = blockIdx.x & 15;
    const int q0  = blockIdx.y << 6;
    const int tid = threadIdx.x;
    const int w    = tid >> 5;
    const int lane = tid & 31;
    const int qs   = w << 4;          // q-slab base within 64
    const int gid  = lane >> 2;
    const int t    = lane & 3;
    const int sg   = (gid >> 1) + (gid & 1) * 4;  // permuted key column

    const float* Qb = g_Q + ((size_t)b * NQC + q0 + qs) * DIMC + h * HDC;
    const float* Kb = g_K + (size_t)b * NKC * DIMC + h * HDC;
    const float* Vb = g_V + (size_t)b * NKC * DIMC + h * D2C;

    // Q fragments, both streams (persist; pre-scaled by SCALE*log2e)
    uint32_t aQ[2][4][4];
    #pragma unroll
    for (int s = 0; s < 2; s++) {
        const float* qr0 = Qb + (size_t)gid * DIMC + s * (HC * HDC);
        const float* qr1 = qr0 + (size_t)8 * DIMC;
        #pragma unroll
        for (int k = 0; k < 4; k++) {
            aQ[s][k][0] = f2tf(qr0[k * 8 + t] * SCALE_L2E_F);
            aQ[s][k][1] = f2tf(qr1[k * 8 + t] * SCALE_L2E_F);
            aQ[s][k][2] = f2tf(qr0[k * 8 + t + 4] * SCALE_L2E_F);
            aQ[s][k][3] = f2tf(qr1[k * 8 + t + 4] * SCALE_L2E_F);
        }
    }

    float lacc[2][2] = {{0.0f, 0.0f}, {0.0f, 0.0f}};
    float O[2][8][4];
    #pragma unroll
    for (int s = 0; s < 2; s++)
        #pragma unroll
        for (int n = 0; n < 8; n++)
            #pragma unroll
            for (int r = 0; r < 4; r++) O[s][n][r] = 0.0f;

    // async tile prefetch: 1024 16B chunks (512 K + 512 V), 8 per thread
    auto prefetch = [&](int k0, int st) {
        float* base = sma + st * 4608;
        #pragma unroll
        for (int i = 0; i < 8; i++) {
            int c = tid + 128 * i;
            if (c < 512) {
                int str = c >> 8;
                int key = (c >> 3) & 31;
                int d4  = (c & 7) * 4;
                cpa16(s2u(base + str * 1152 + key * 36 + d4),
                      Kb + (size_t)(k0 + key) * DIMC + str * (HC * HDC) + d4);
            } else {
                int cc  = c - 512;
                int key = cc >> 4;
                int d4  = (cc & 15) * 4;
                cpa16(s2u(base + 2304 + key * 72 + d4),
                      Vb + (size_t)(k0 + key) * DIMC + d4);
            }
        }
    };

    prefetch(0, 0);
    CP_COMMIT();

    const int NIT = NKC / 32;  // 64
    for (int kt = 0; kt < NIT; kt++) {
        const int cur = kt & 1;
        CP_WAIT0();        // stage cur arrived
        __syncthreads();   // visible to all; all done with stage cur^1
        if (kt + 1 < NIT) {
            prefetch((kt + 1) * 32, cur ^ 1);
            CP_COMMIT();
        }

        const float* sK0 = sma + cur * 4608;                 // stream0 K [32][36]
        const float* sK1 = sK0 + 1152;                       // stream1 K
        const float* sV  = sma + cur * 4608 + 2304;          // V [32][72]

        // S[s] = Q[s](16x32) x K[s]^T (key columns permuted by sg)
        float S[2][4][4];
        #pragma unroll
        for (int s = 0; s < 2; s++)
            #pragma unroll
            for (int n = 0; n < 4; n++)
                #pragma unroll
                for (int r = 0; r < 4; r++) S[s][n][r] = 0.0f;

        #pragma unroll
        for (int k = 0; k < 4; k++) {
            #pragma unroll
            for (int n = 0; n < 4; n++) {
                uint32_t bf0[2], bf1[2];
                bf0[0] = __float_as_uint(sK0[(n * 8 + sg) * 36 + k * 8 + t]);
                bf0[1] = __float_as_uint(sK0[(n * 8 + sg) * 36 + k * 8 + t + 4]);
                bf1[0] = __float_as_uint(sK1[(n * 8 + sg) * 36 + k * 8 + t]);
                bf1[1] = __float_as_uint(sK1[(n * 8 + sg) * 36 + k * 8 + t + 4]);
                mma8(S[0][n], aQ[0][k], bf0);
                mma8(S[1][n], aQ[1][k], bf1);
            }
        }

        // exp (no max), accumulate l partials, build A-frags in place
        uint32_t ap[2][4][4];
        #pragma unroll
        for (int s = 0; s < 2; s++) {
            #pragma unroll
            for (int n = 0; n < 4; n++) {
                float p0 = ex2(S[s][n][0]);
                float p1 = ex2(S[s][n][1]);
                float p2 = ex2(S[s][n][2]);
                float p3 = ex2(S[s][n][3]);
                lacc[s][0] += p0 + p1;
                lacc[s][1] += p2 + p3;
                ap[s][n][0] = f2tf(p0);
                ap[s][n][1] = f2tf(p2);
                ap[s][n][2] = f2tf(p1);
                ap[s][n][3] = f2tf(p3);
            }
        }

        // O[s] += P[s](16x32) x V(32x64) — ONE V-frag load serves both streams
        #pragma unroll
        for (int k = 0; k < 4; k++) {
            #pragma unroll
            for (int n = 0; n < 8; n++) {
                uint32_t bf[2];
                bf[0] = __float_as_uint(sV[(k * 8 + t) * 72 + n * 8 + gid]);
                bf[1] = __float_as_uint(sV[(k * 8 + t + 4) * 72 + n * 8 + gid]);
                mma8(O[0][n], ap[0][k], bf);
                mma8(O[1][n], ap[1][k], bf);
            }
        }
    }

    // final l reductions across the quad
    #pragma unroll
    for (int s = 0; s < 2; s++) {
        lacc[s][0] += __shfl_xor_sync(0xffffffffu, lacc[s][0], 1);
        lacc[s][0] += __shfl_xor_sync(0xffffffffu, lacc[s][0], 2);
        lacc[s][1] += __shfl_xor_sync(0xffffffffu, lacc[s][1], 1);
        lacc[s][1] += __shfl_xor_sync(0xffffffffu, lacc[s][1], 2);
    }

    // ---------------- epilogue (fully warp-local) ----------------
    const float lam = g_lam;
    const float i00 = 1.0f / lacc[0][0];
    const float i01 = 1.0f / lacc[0][1];
    const float i10 = lam / lacc[1][0];
    const float i11 = lam / lacc[1][1];

    float out[8][4];
    float ss0 = 0.0f, ss1 = 0.0f;
    #pragma unroll
    for (int n = 0; n < 8; n++) {
        out[n][0] = O[0][n][0] * i00 - O[1][n][0] * i10;
        out[n][1] = O[0][n][1] * i00 - O[1][n][1] * i10;
        out[n][2] = O[0][n][2] * i01 - O[1][n][2] * i11;
        out[n][3] = O[0][n][3] * i01 - O[1][n][3] * i11;
        ss0 += out[n][0] * out[n][0] + out[n][1] * out[n][1];
        ss1 += out[n][2] * out[n][2] + out[n][3] * out[n][3];
    }
    ss0 += __shfl_xor_sync(0xffffffffu, ss0, 1);
    ss0 += __shfl_xor_sync(0xffffffffu, ss0, 2);
    ss1 += __shfl_xor_sync(0xffffffffu, ss1, 1);
    ss1 += __shfl_xor_sync(0xffffffffu, ss1, 2);
    float r0 = rsqrtf(ss0 * (1.0f / 64.0f) + EPS_F);
    float r1 = rsqrtf(ss1 * (1.0f / 64.0f) + EPS_F);

    float* d0 = g_A + ((size_t)b * NQC + q0 + qs + gid) * DIMC + h * D2C;
    float* d1 = d0 + (size_t)8 * DIMC;
    #pragma unroll
    for (int n = 0; n < 8; n++) {
        int c0 = n * 8 + 2 * t;
        float w0 = subw[c0] * ONE_MINUS_LAMBDA_F;
        float w1 = subw[c0 + 1] * ONE_MINUS_LAMBDA_F;
        *(float2*)(d0 + c0) = make_float2(f2tff(out[n][0] * r0 * w0),
                                          f2tff(out[n][1] * r0 * w1));
        *(float2*)(d1 + c0) = make_float2(f2tff(out[n][2] * r1 * w0),
                                          f2tff(out[n][3] * r1 * w1));
    }
}

// ---------------------------------------------------------------------------
extern "C" void kernel_launch(void* const* d_in, const int* in_sizes, int n_in,
                              void* d_out, int out_size) {
    const float* query = (const float*)d_in[0];
    const float* key_  = (const float*)d_in[1];
    const float* value = (const float*)d_in[2];
    const float* Wq    = (const float*)d_in[3];
    const float* Wk    = (const float*)d_in[4];
    const float* Wv    = (const float*)d_in[5];
    const float* Wp    = (const float*)d_in[6];
    const float* bp    = (const float*)d_in[7];
    const float* lq1   = (const float*)d_in[8];
    const float* lk1   = (const float*)d_in[9];
    const float* lq2   = (const float*)d_in[10];
    const float* lk2   = (const float*)d_in[11];
    const float* subw  = (const float*)d_in[12];
    float* out = (float*)d_out;

    static bool attr_done = false;
    if (!attr_done) {
        cudaFuncSetAttribute(qkv_gemm, cudaFuncAttributeMaxDynamicSharedMemorySize,
                             GEMM_SMEM_BYTES);
        cudaFuncSetAttribute(out_gemm, cudaFuncAttributeMaxDynamicSharedMemorySize,
                             GEMM_SMEM_BYTES);
        attr_done = true;
    }

    lam_kernel<<<1, 32>>>(lq1, lk1, lq2, lk2);

    dim3 pgrid(512, 1, 7);
    prepass_kernel<<<pgrid, 256>>>(query, key_, value, Wq, Wk, Wv, Wp);

    dim3 qkvgrid(DIMC / 128, (BC * NQC) / 128, 3);  // (8, 32, 3)
    qkv_gemm<<<qkvgrid, 256, GEMM_SMEM_BYTES>>>();

    dim3 agrid(BC * HC, NQC / 64);  // (32, 32)
    attn_kernel<<<agrid, 128>>>(subw);

    dim3 ogrid(DIMC / 128, (BC * NQC) / 128);  // (8, 32)
    out_gemm<<<ogrid, 256, GEMM_SMEM_BYTES>>>(bp, out);
}